// round 9
// baseline (speedup 1.0000x reference)
#include <cuda_runtime.h>
#include <cuda_fp16.h>
#include <cstdint>
#include <math.h>

#define DIM   1024
#define BATCH 4
#define SEQ   2048
#define MTOT  (BATCH * SEQ)
#define NQKV  (3 * DIM)                    // fused QKV output width

#define BK          64                     // K elems per chunk
#define PITCH_H     72                     // fp16 per smem row (64 + pad)
#define PITCH_B     (PITCH_H * 2)          // 144 bytes
#define TILE_B      (128 * PITCH_B)        // 18432 B per operand tile
#define STAGE_B     (2 * TILE_B)           // 36864
#define SMEM_DYN    (2 * STAGE_B)          // 73728 (double buffer)

// -------- scratch (__device__ globals per allocation-free rule) --------
__device__ __half g_xh  [(long)MTOT * DIM];      // 16 MB  fp16 x
__device__ __half g_wh  [(long)NQKV * DIM];      //  6 MB  fp16 W rows (q,k,v stacked)
__device__ float  g_bc  [NQKV];                  // concat bias
__device__ __half g_qkv [(long)MTOT * NQKV];     // 48 MB  [q | k | v] per row
__device__ __half g_vT  [(long)DIM * MTOT];      // 16 MB  vT[d][b*SEQ+m]
__device__ float  g_s   [(long)BATCH * SEQ * SEQ]; // 64 MB logits
__device__ __half g_p   [(long)MTOT * SEQ];      // 32 MB  probabilities

// ---------------------------------------------------------------------------
__device__ __forceinline__ void cp16(void* s, const void* g) {
    uint32_t sa = (uint32_t)__cvta_generic_to_shared(s);
    asm volatile("cp.async.cg.shared.global [%0], [%1], 16;"
                 :: "r"(sa), "l"(g) : "memory");
}
__device__ __forceinline__ void cp_commit() {
    asm volatile("cp.async.commit_group;" ::: "memory");
}
template <int N>
__device__ __forceinline__ void cp_wait() {
    asm volatile("cp.async.wait_group %0;" :: "n"(N) : "memory");
}
__device__ __forceinline__ void ldmx4(uint32_t* r, uint32_t addr) {
    asm volatile("ldmatrix.sync.aligned.m8n8.x4.shared.b16 {%0,%1,%2,%3}, [%4];"
                 : "=r"(r[0]), "=r"(r[1]), "=r"(r[2]), "=r"(r[3]) : "r"(addr));
}
__device__ __forceinline__ void mma16816(float* c, const uint32_t* a, const uint32_t* b) {
    asm volatile(
        "mma.sync.aligned.m16n8k16.row.col.f32.f16.f16.f32 "
        "{%0,%1,%2,%3}, {%4,%5,%6,%7}, {%8,%9}, {%0,%1,%2,%3};"
        : "+f"(c[0]), "+f"(c[1]), "+f"(c[2]), "+f"(c[3])
        : "r"(a[0]), "r"(a[1]), "r"(a[2]), "r"(a[3]), "r"(b[0]), "r"(b[1]));
}

// ---------------------------------------------------------------------------
// fp16 NT GEMM: C = scale * (A @ B^T) (+ bias)
// MODE 0: C half [m][n] + bias       MODE 2: C float [m][n] * scale
// Double-buffered (BK=64). Loop: wait(all) -> bar -> issue load(i+1) -> compute(i).
// Barrier guarantees every warp finished compute(i-1), so slot (i+1)&1 is free;
// load(i+1) overlaps compute(i) (~2000 cyc >> DRAM latency).
// ---------------------------------------------------------------------------
template <int MODE>
__global__ __launch_bounds__(256, 2) void gemm_h(
    const __half* __restrict__ A, const __half* __restrict__ B,
    const float* __restrict__ bias, void* __restrict__ Cv,
    int lda, int ldb, int ldc, int K, float scale,
    int aZrow, int bZrow, int bZcol, long cZ)
{
    extern __shared__ __align__(16) char dsmem[];

    const int tid  = threadIdx.x;
    const int wid  = tid >> 5;
    const int lane = tid & 31;
    const int wm   = wid & 1;          // 2 M-slabs of 64
    const int wn   = wid >> 1;         // 4 N-slabs of 32
    const int r    = lane >> 2;
    const int cpr  = lane & 3;
    const int lj   = lane >> 3;        // ldmatrix address group
    const int lr   = lane & 7;

    const int z  = blockIdx.z;
    const int m0 = blockIdx.y * 128;
    const int n0 = blockIdx.x * 128;

    const __half* Ag = A + (long)(z * aZrow + m0) * lda;
    const __half* Bg = B + (long)(z * bZrow + n0) * ldb + (long)z * bZcol;

    const int ldrow = tid >> 1;        // loader row 0..127
    const int ldh   = tid & 1;         // half-row (64B) selector

    const uint32_t smem0 = (uint32_t)__cvta_generic_to_shared(dsmem);

    // ldmatrix per-thread byte offsets within a tile
    uint32_t aoff[4], boff[2];
#pragma unroll
    for (int mt = 0; mt < 4; mt++)
        aoff[mt] = (uint32_t)((wm * 64 + mt * 16 + (lj & 1) * 8 + lr) * PITCH_B
                              + (lj >> 1) * 16);
#pragma unroll
    for (int pq = 0; pq < 2; pq++)
        boff[pq] = (uint32_t)((wn * 32 + (pq * 2 + (lj >> 1)) * 8 + lr) * PITCH_B
                              + (lj & 1) * 16);

    float acc[4][4][4];
#pragma unroll
    for (int i = 0; i < 4; i++)
#pragma unroll
        for (int j = 0; j < 4; j++)
#pragma unroll
            for (int t = 0; t < 4; t++) acc[i][j][t] = 0.f;

    const int nch = K / BK;

    auto load_stage = [&](int slot, int kpos) {
        char* sa = dsmem + slot * STAGE_B;
        char* sb = sa + TILE_B;
        // each thread: 4 cp16 for A row-half + 4 for B row-half
#pragma unroll
        for (int jseg = 0; jseg < 4; jseg++) {
            int off = ldh * 64 + jseg * 16;          // byte offset in 128B row
            cp16(sa + ldrow * PITCH_B + off,
                 Ag + (long)ldrow * lda + kpos + ldh * 32 + jseg * 8);
            cp16(sb + ldrow * PITCH_B + off,
                 Bg + (long)ldrow * ldb + kpos + ldh * 32 + jseg * 8);
        }
    };

    load_stage(0, 0);
    cp_commit();

    for (int i = 0; i < nch; i++) {
        cp_wait<0>();
        __syncthreads();

        if (i + 1 < nch) load_stage((i + 1) & 1, (i + 1) * BK);
        cp_commit();

        const uint32_t sa32 = smem0 + (i & 1) * STAGE_B;
        const uint32_t sb32 = sa32 + TILE_B;

#pragma unroll
        for (int ks = 0; ks < 4; ks++) {
            uint32_t af[4][4], bf[2][4];
#pragma unroll
            for (int mt = 0; mt < 4; mt++)
                ldmx4(af[mt], sa32 + aoff[mt] + ks * 32);
#pragma unroll
            for (int pq = 0; pq < 2; pq++)
                ldmx4(bf[pq], sb32 + boff[pq] + ks * 32);
#pragma unroll
            for (int mt = 0; mt < 4; mt++)
#pragma unroll
                for (int nt = 0; nt < 4; nt++)
                    mma16816(acc[mt][nt], af[mt], &bf[nt >> 1][(nt & 1) * 2]);
        }
    }

    // ---- epilogue ----
#pragma unroll
    for (int mt = 0; mt < 4; mt++) {
#pragma unroll
        for (int nt = 0; nt < 4; nt++) {
            int grow0 = m0 + wm * 64 + mt * 16 + r;
            int gcol  = n0 + wn * 32 + nt * 8 + cpr * 2;
            float* c = acc[mt][nt];
            if (MODE == 0) {
                __half* C = (__half*)Cv;
                float b0 = bias[gcol], b1 = bias[gcol + 1];
                *reinterpret_cast<__half2*>(&C[(long)grow0 * ldc + gcol]) =
                    __floats2half2_rn(c[0] + b0, c[1] + b1);
                *reinterpret_cast<__half2*>(&C[(long)(grow0 + 8) * ldc + gcol]) =
                    __floats2half2_rn(c[2] + b0, c[3] + b1);
            } else {
                float* C = (float*)Cv + z * cZ;
                *reinterpret_cast<float2*>(&C[(long)grow0 * ldc + gcol]) =
                    make_float2(c[0] * scale, c[1] * scale);
                *reinterpret_cast<float2*>(&C[(long)(grow0 + 8) * ldc + gcol]) =
                    make_float2(c[2] * scale, c[3] * scale);
            }
        }
    }
}

// ---------------------------------------------------------------------------
// fp32 -> fp16 converts
// ---------------------------------------------------------------------------
__global__ __launch_bounds__(256) void conv_x(
    const float* __restrict__ in, __half* __restrict__ out, long n4)
{
    long i = (long)blockIdx.x * 256 + threadIdx.x;
    if (i >= n4) return;
    float4 v = reinterpret_cast<const float4*>(in)[i];
    __half2 h[2];
    h[0] = __floats2half2_rn(v.x, v.y);
    h[1] = __floats2half2_rn(v.z, v.w);
    *reinterpret_cast<uint2*>(&out[i * 4]) = *reinterpret_cast<uint2*>(h);
}

// all three W's in one launch (dst contiguous)
__global__ __launch_bounds__(256) void conv_w(
    const float* __restrict__ w0, const float* __restrict__ w1,
    const float* __restrict__ w2, __half* __restrict__ out)
{
    const long per = (long)DIM * DIM / 4;
    long i = (long)blockIdx.x * 256 + threadIdx.x;
    if (i >= 3 * per) return;
    const float* src = (i < per) ? w0 : (i < 2 * per) ? w1 : w2;
    long j = (i < per) ? i : (i < 2 * per) ? i - per : i - 2 * per;
    float4 v = reinterpret_cast<const float4*>(src)[j];
    __half2 h[2];
    h[0] = __floats2half2_rn(v.x, v.y);
    h[1] = __floats2half2_rn(v.z, v.w);
    *reinterpret_cast<uint2*>(&out[i * 4]) = *reinterpret_cast<uint2*>(h);
}

__global__ void concat_bias(const float* a, const float* b, const float* c,
                            float* o)
{
    int i = blockIdx.x * 256 + threadIdx.x;
    if (i < DIM) { o[i] = a[i]; o[DIM + i] = b[i]; o[2 * DIM + i] = c[i]; }
}

// ---------------------------------------------------------------------------
// Transpose v slice of qkv ([m][2048+d], ld NQKV) -> vT [d][m]
// ---------------------------------------------------------------------------
__global__ __launch_bounds__(256) void transpose_v(
    const __half* __restrict__ src, __half* __restrict__ dst)
{
    __shared__ __half t[32][33];
    int d0 = blockIdx.x * 32, m0 = blockIdx.y * 32;
    int tx = threadIdx.x & 31, ty = threadIdx.x >> 5;   // 32 x 8
#pragma unroll
    for (int i = 0; i < 4; i++)
        t[ty + i * 8][tx] = src[(long)(m0 + ty + i * 8) * NQKV + 2 * DIM + d0 + tx];
    __syncthreads();
#pragma unroll
    for (int i = 0; i < 4; i++)
        dst[(long)(d0 + ty + i * 8) * MTOT + m0 + tx] = t[tx][ty + i * 8];
}

// ---------------------------------------------------------------------------
// Row softmax over SEQ fp32 logits -> fp16 probabilities
// ---------------------------------------------------------------------------
__global__ __launch_bounds__(256) void softmax_kernel(
    const float* __restrict__ S, __half* __restrict__ P)
{
    const float* p = S + (long)blockIdx.x * SEQ;
    __half* o = P + (long)blockIdx.x * SEQ;
    const int tid = threadIdx.x;

    float4 v0 = reinterpret_cast<const float4*>(p)[tid * 2 + 0];
    float4 v1 = reinterpret_cast<const float4*>(p)[tid * 2 + 1];

    __shared__ float red[256];

    float mx = fmaxf(fmaxf(fmaxf(v0.x, v0.y), fmaxf(v0.z, v0.w)),
                     fmaxf(fmaxf(v1.x, v1.y), fmaxf(v1.z, v1.w)));
    red[tid] = mx;
    __syncthreads();
#pragma unroll
    for (int s = 128; s > 0; s >>= 1) {
        if (tid < s) red[tid] = fmaxf(red[tid], red[tid + s]);
        __syncthreads();
    }
    const float rmax = red[0];
    __syncthreads();

    v0.x = expf(v0.x - rmax); v0.y = expf(v0.y - rmax);
    v0.z = expf(v0.z - rmax); v0.w = expf(v0.w - rmax);
    v1.x = expf(v1.x - rmax); v1.y = expf(v1.y - rmax);
    v1.z = expf(v1.z - rmax); v1.w = expf(v1.w - rmax);

    red[tid] = (v0.x + v0.y + v0.z + v0.w) + (v1.x + v1.y + v1.z + v1.w);
    __syncthreads();
#pragma unroll
    for (int s = 128; s > 0; s >>= 1) {
        if (tid < s) red[tid] += red[tid + s];
        __syncthreads();
    }
    const float inv = 1.f / red[0];

    __half2 h[4];
    h[0] = __floats2half2_rn(v0.x * inv, v0.y * inv);
    h[1] = __floats2half2_rn(v0.z * inv, v0.w * inv);
    h[2] = __floats2half2_rn(v1.x * inv, v1.y * inv);
    h[3] = __floats2half2_rn(v1.z * inv, v1.w * inv);
    *reinterpret_cast<uint4*>(&o[tid * 8]) = *reinterpret_cast<uint4*>(h);
}

// ---------------------------------------------------------------------------
extern "C" void kernel_launch(void* const* d_in, const int* in_sizes, int n_in,
                              void* d_out, int out_size)
{
    const float* x  = (const float*)d_in[0];
    const float* Wq = (const float*)d_in[1];
    const float* bq = (const float*)d_in[2];
    const float* Wk = (const float*)d_in[3];
    const float* bk = (const float*)d_in[4];
    const float* Wv = (const float*)d_in[5];
    const float* bv = (const float*)d_in[6];
    float* out = (float*)d_out;

    __half *xh, *wh, *qkv, *vT, *p;
    float *s, *bc;
    cudaGetSymbolAddress((void**)&xh,  g_xh);
    cudaGetSymbolAddress((void**)&wh,  g_wh);
    cudaGetSymbolAddress((void**)&bc,  g_bc);
    cudaGetSymbolAddress((void**)&qkv, g_qkv);
    cudaGetSymbolAddress((void**)&vT,  g_vT);
    cudaGetSymbolAddress((void**)&s,   g_s);
    cudaGetSymbolAddress((void**)&p,   g_p);

    cudaFuncSetAttribute(gemm_h<0>, cudaFuncAttributeMaxDynamicSharedMemorySize, SMEM_DYN);
    cudaFuncSetAttribute(gemm_h<2>, cudaFuncAttributeMaxDynamicSharedMemorySize, SMEM_DYN);

    // 0) fp16 conversions + bias concat
    conv_x<<<(MTOT * DIM / 4 + 255) / 256, 256>>>(x, xh, (long)MTOT * DIM / 4);
    conv_w<<<(3 * DIM * DIM / 4 + 255) / 256, 256>>>(Wq, Wk, Wv, wh);
    concat_bias<<<(DIM + 255) / 256, 256>>>(bq, bk, bv, bc);

    // 1) fused QKV: qkv[8192][3072] = xh @ wh^T + bc  (K=1024)
    dim3 gQKV(NQKV / 128, MTOT / 128, 1);
    gemm_h<0><<<gQKV, 256, SMEM_DYN>>>(xh, wh, bc, qkv,
                                       DIM, DIM, NQKV, DIM, 1.f, 0, 0, 0, 0);

    // 1b) transpose v slice -> vT
    dim3 gT(DIM / 32, MTOT / 32);
    transpose_v<<<gT, 256>>>(qkv, vT);

    // 2) S = (q @ k^T) * DIM^-0.5, batched over z
    dim3 gS(SEQ / 128, SEQ / 128, BATCH);
    gemm_h<2><<<gS, 256, SMEM_DYN>>>(qkv, qkv + DIM, nullptr, s,
                                     NQKV, NQKV, SEQ, DIM, 0.03125f,
                                     SEQ, SEQ, 0, (long)SEQ * SEQ);

    // 3) softmax rows -> fp16 P
    softmax_kernel<<<MTOT, 256>>>(s, p);

    // 4) out = P @ vT^T, batched over z
    dim3 gO(DIM / 128, SEQ / 128, BATCH);
    gemm_h<2><<<gO, 256, SMEM_DYN>>>(p, vT, nullptr, out,
                                     SEQ, MTOT, DIM, SEQ, 1.f,
                                     SEQ, 0, SEQ, (long)SEQ * DIM);
}